// round 2
// baseline (speedup 1.0000x reference)
#include <cuda_runtime.h>
#include <math.h>

#define NN   50000
#define EE   800000
#define ETOT (EE + NN)
#define H1N  4
#define C1   256   // H1*64
#define C2   64

// ---------------- scratch (device globals; no allocations allowed) ----------
__device__ float    g_h1[(size_t)NN * C1];      // x @ W1
__device__ float    g_out1[(size_t)NN * C1];    // layer-1 aggregate (init b1), then elu -> layer2 input
__device__ float    g_h2[(size_t)NN * C2];      // h @ W2
__device__ float    g_alsrc1[NN * H1N], g_aldst1[NN * H1N];
__device__ unsigned g_mxenc1[NN * H1N];
__device__ float    g_mx1[NN * H1N], g_denom1[NN * H1N];
__device__ float    g_logits1[(size_t)ETOT * H1N];
__device__ float    g_alsrc2[NN], g_aldst2[NN];
__device__ unsigned g_mxenc2[NN];
__device__ float    g_mx2[NN], g_denom2[NN];
__device__ float    g_logits2[ETOT];

// ---------------- helpers ---------------------------------------------------
__device__ __forceinline__ unsigned fenc(float f) {
    unsigned b = __float_as_uint(f);
    return (b & 0x80000000u) ? ~b : (b | 0x80000000u);
}
__device__ __forceinline__ float fdec(unsigned u) {
    unsigned b = (u & 0x80000000u) ? (u & 0x7FFFFFFFu) : ~u;
    return __uint_as_float(b);
}
__device__ __forceinline__ void red_add_f32x4(float* addr, float4 v) {
    asm volatile("red.global.add.v4.f32 [%0], {%1,%2,%3,%4};"
                 :: "l"(addr), "f"(v.x), "f"(v.y), "f"(v.z), "f"(v.w)
                 : "memory");
}

// ---------------- init: biases into accumulators, zero softmax state --------
__global__ void init_kernel(const float* __restrict__ b1,
                            const float* __restrict__ b2,
                            float* __restrict__ dout) {
    int tid = blockIdx.x * blockDim.x + threadIdx.x;
    if (tid < NN * C1) g_out1[tid] = b1[tid & (C1 - 1)];
    if (tid < NN * C2) dout[tid]   = b2[tid & (C2 - 1)];
    if (tid < NN * H1N) { g_mxenc1[tid] = 0u; g_denom1[tid] = 0.0f; }
    if (tid < NN)       { g_mxenc2[tid] = 0u; g_denom2[tid] = 0.0f; }
}

// ---------------- tiled fp32 GEMM: C[M,N] = A[M,K] @ B[K,N] -----------------
// 64x64 tile, 256 threads, 4x4 microtile, BK=16. N % 64 == 0, K % 16 == 0.
__global__ void gemm_tiled(const float* __restrict__ A, const float* __restrict__ B,
                           float* __restrict__ C, int M, int K, int N) {
    __shared__ float As[16][64];
    __shared__ float Bs[16][64];
    const int t  = threadIdx.x;
    const int tx = t & 15, ty = t >> 4;
    const int row0 = blockIdx.y * 64, col0 = blockIdx.x * 64;

    float acc[4][4] = {};

    for (int k0 = 0; k0 < K; k0 += 16) {
        // A tile: thread loads float4 at (row0 + t/4, k0 + (t%4)*4), store transposed
        int ar = t >> 2, ac = (t & 3) * 4;
        float4 av = make_float4(0.f, 0.f, 0.f, 0.f);
        if (row0 + ar < M)
            av = *(const float4*)&A[(size_t)(row0 + ar) * K + k0 + ac];
        As[ac + 0][ar] = av.x; As[ac + 1][ar] = av.y;
        As[ac + 2][ar] = av.z; As[ac + 3][ar] = av.w;
        // B tile: thread loads float4 at (k0 + t/16, col0 + (t%16)*4)
        int br = t >> 4, bc = (t & 15) * 4;
        *(float4*)&Bs[br][bc] = *(const float4*)&B[(size_t)(k0 + br) * N + col0 + bc];
        __syncthreads();

        #pragma unroll
        for (int kk = 0; kk < 16; kk++) {
            float4 a = *(const float4*)&As[kk][ty * 4];
            float4 b = *(const float4*)&Bs[kk][tx * 4];
            acc[0][0] += a.x * b.x; acc[0][1] += a.x * b.y; acc[0][2] += a.x * b.z; acc[0][3] += a.x * b.w;
            acc[1][0] += a.y * b.x; acc[1][1] += a.y * b.y; acc[1][2] += a.y * b.z; acc[1][3] += a.y * b.w;
            acc[2][0] += a.z * b.x; acc[2][1] += a.z * b.y; acc[2][2] += a.z * b.z; acc[2][3] += a.z * b.w;
            acc[3][0] += a.w * b.x; acc[3][1] += a.w * b.y; acc[3][2] += a.w * b.z; acc[3][3] += a.w * b.w;
        }
        __syncthreads();
    }

    #pragma unroll
    for (int i = 0; i < 4; i++) {
        int r = row0 + ty * 4 + i;
        if (r < M) {
            float4 o = make_float4(acc[i][0], acc[i][1], acc[i][2], acc[i][3]);
            *(float4*)&C[(size_t)r * N + col0 + tx * 4] = o;
        }
    }
}

// ---------------- per-(node, head) attention coefficients -------------------
template <int H>
__global__ void node_al(const float* __restrict__ feat,
                        const float* __restrict__ a_src, const float* __restrict__ a_dst,
                        float* __restrict__ als, float* __restrict__ ald) {
    int tid = blockIdx.x * blockDim.x + threadIdx.x;
    if (tid >= NN * H) return;
    int node = tid / H, h = tid - node * H;
    const float* row = &feat[(size_t)node * (H * 64) + h * 64];
    const float* as  = &a_src[h * 64];
    const float* ad  = &a_dst[h * 64];
    float ss = 0.f, dd = 0.f;
    #pragma unroll
    for (int i = 0; i < 64; i += 4) {
        float4 v  = *(const float4*)&row[i];
        float4 va = *(const float4*)&as[i];
        float4 vb = *(const float4*)&ad[i];
        ss += v.x * va.x + v.y * va.y + v.z * va.z + v.w * va.w;
        dd += v.x * vb.x + v.y * vb.y + v.z * vb.z + v.w * vb.w;
    }
    als[tid] = ss;
    ald[tid] = dd;
}

// ---------------- edge pass 1: leaky-relu logits + segment max --------------
template <int H>
__global__ void edge_logits(const int* __restrict__ ei,
                            const float* __restrict__ als, const float* __restrict__ ald,
                            float* __restrict__ logits, unsigned* __restrict__ mxenc) {
    int e = blockIdx.x * blockDim.x + threadIdx.x;
    if (e >= ETOT) return;
    int s, d;
    if (e < EE) { s = ei[e]; d = ei[e + EE]; }
    else        { s = d = e - EE; }
    #pragma unroll
    for (int h = 0; h < H; h++) {
        float l = als[s * H + h] + ald[d * H + h];
        l = l > 0.f ? l : 0.2f * l;
        logits[(size_t)e * H + h] = l;
        atomicMax(&mxenc[d * H + h], fenc(l));
    }
}

// ---------------- decode encoded max back to float --------------------------
__global__ void decode_mx(const unsigned* __restrict__ enc_, float* __restrict__ mx, int n) {
    int tid = blockIdx.x * blockDim.x + threadIdx.x;
    if (tid < n) mx[tid] = fdec(enc_[tid]);
}

// ---------------- edge pass 2: exp + segment sum ----------------------------
template <int H>
__global__ void edge_exp(const int* __restrict__ ei,
                         float* __restrict__ logits, const float* __restrict__ mx,
                         float* __restrict__ denom) {
    int e = blockIdx.x * blockDim.x + threadIdx.x;
    if (e >= ETOT) return;
    int d = (e < EE) ? ei[e + EE] : (e - EE);
    #pragma unroll
    for (int h = 0; h < H; h++) {
        float v = __expf(logits[(size_t)e * H + h] - mx[d * H + h]);
        logits[(size_t)e * H + h] = v;
        atomicAdd(&denom[d * H + h], v);
    }
}

// ---------------- edge pass 3: gather, scale, scatter-add -------------------
// thread = (edge, float4-chunk). TC = H*64 feature columns.
template <int H, int TC>
__global__ void edge_scatter(const int* __restrict__ ei,
                             const float* __restrict__ feat,
                             const float* __restrict__ w,      // exp weights per edge/head
                             const float* __restrict__ denom,
                             float* __restrict__ out) {
    const int CH = TC / 4;
    long long gid = (long long)blockIdx.x * blockDim.x + threadIdx.x;
    int e = (int)(gid / CH);
    if (e >= ETOT) return;
    int c4 = (int)(gid - (long long)e * CH) * 4;
    int s, d;
    if (e < EE) { s = ei[e]; d = ei[e + EE]; }
    else        { s = d = e - EE; }
    int h = c4 >> 6;
    float alpha = w[(size_t)e * H + h] / fmaxf(denom[d * H + h], 1e-16f);
    float4 hv = *(const float4*)&feat[(size_t)s * TC + c4];
    red_add_f32x4(&out[(size_t)d * TC + c4],
                  make_float4(hv.x * alpha, hv.y * alpha, hv.z * alpha, hv.w * alpha));
}

// ---------------- elu epilogue on layer-1 output ----------------------------
__global__ void elu_kernel(int n) {
    int tid = blockIdx.x * blockDim.x + threadIdx.x;
    if (tid >= n) return;
    float v = g_out1[tid];
    g_out1[tid] = v > 0.f ? v : expm1f(v);
}

// ---------------- launch ----------------------------------------------------
extern "C" void kernel_launch(void* const* d_in, const int* in_sizes, int n_in,
                              void* d_out, int out_size) {
    (void)n_in; (void)in_sizes; (void)out_size;
    const float* x      = (const float*)d_in[0];
    const int*   ei     = (const int*)d_in[1];     // int32: JAX downgrades int64 without x64
    const float* W1     = (const float*)d_in[2];
    const float* a_src1 = (const float*)d_in[3];
    const float* a_dst1 = (const float*)d_in[4];
    const float* b1     = (const float*)d_in[5];
    const float* W2     = (const float*)d_in[6];
    const float* a_src2 = (const float*)d_in[7];
    const float* a_dst2 = (const float*)d_in[8];
    const float* b2     = (const float*)d_in[9];
    float* dout = (float*)d_out;

    float *h1, *out1, *h2, *alsrc1, *aldst1, *mx1, *denom1, *logits1;
    float *alsrc2, *aldst2, *mx2, *denom2, *logits2;
    unsigned *mxenc1, *mxenc2;
    cudaGetSymbolAddress((void**)&h1,      g_h1);
    cudaGetSymbolAddress((void**)&out1,    g_out1);
    cudaGetSymbolAddress((void**)&h2,      g_h2);
    cudaGetSymbolAddress((void**)&alsrc1,  g_alsrc1);
    cudaGetSymbolAddress((void**)&aldst1,  g_aldst1);
    cudaGetSymbolAddress((void**)&mxenc1,  g_mxenc1);
    cudaGetSymbolAddress((void**)&mx1,     g_mx1);
    cudaGetSymbolAddress((void**)&denom1,  g_denom1);
    cudaGetSymbolAddress((void**)&logits1, g_logits1);
    cudaGetSymbolAddress((void**)&alsrc2,  g_alsrc2);
    cudaGetSymbolAddress((void**)&aldst2,  g_aldst2);
    cudaGetSymbolAddress((void**)&mxenc2,  g_mxenc2);
    cudaGetSymbolAddress((void**)&mx2,     g_mx2);
    cudaGetSymbolAddress((void**)&denom2,  g_denom2);
    cudaGetSymbolAddress((void**)&logits2, g_logits2);

    const int T = 256;
    // 0) init accumulators (bias broadcast) + softmax state
    init_kernel<<<(NN * C1 + T - 1) / T, T>>>(b1, b2, dout);
    // 1) h1 = x @ W1
    {
        dim3 g(C1 / 64, (NN + 63) / 64);
        gemm_tiled<<<g, 256>>>(x, W1, h1, NN, 128, C1);
    }
    // 2) attention coefficients, layer 1
    node_al<H1N><<<(NN * H1N + T - 1) / T, T>>>(h1, a_src1, a_dst1, alsrc1, aldst1);
    // 3) softmax passes, layer 1
    edge_logits<H1N><<<(ETOT + T - 1) / T, T>>>(ei, alsrc1, aldst1, logits1, mxenc1);
    decode_mx<<<(NN * H1N + T - 1) / T, T>>>(mxenc1, mx1, NN * H1N);
    edge_exp<H1N><<<(ETOT + T - 1) / T, T>>>(ei, logits1, mx1, denom1);
    // 4) aggregate, layer 1
    {
        long long total = (long long)ETOT * (C1 / 4);
        edge_scatter<H1N, C1><<<(unsigned)((total + T - 1) / T), T>>>(ei, h1, logits1, denom1, out1);
    }
    // 5) elu (bias already folded in via init)
    elu_kernel<<<(NN * C1 + T - 1) / T, T>>>(NN * C1);
    // 6) h2 = elu_out @ W2
    {
        dim3 g(C2 / 64, (NN + 63) / 64);
        gemm_tiled<<<g, 256>>>(out1, W2, h2, NN, C1, C2);
    }
    // 7) attention coefficients, layer 2
    node_al<1><<<(NN + T - 1) / T, T>>>(h2, a_src2, a_dst2, alsrc2, aldst2);
    // 8) softmax passes, layer 2
    edge_logits<1><<<(ETOT + T - 1) / T, T>>>(ei, alsrc2, aldst2, logits2, mxenc2);
    decode_mx<<<(NN + T - 1) / T, T>>>(mxenc2, mx2, NN);
    edge_exp<1><<<(ETOT + T - 1) / T, T>>>(ei, logits2, mx2, denom2);
    // 9) aggregate directly into d_out (pre-initialized to b2)
    {
        long long total = (long long)ETOT * (C2 / 4);
        edge_scatter<1, C2><<<(unsigned)((total + T - 1) / T), T>>>(ei, h2, logits2, denom2, dout);
    }
}

// round 3
// speedup vs baseline: 1.9894x; 1.9894x over previous
#include <cuda_runtime.h>
#include <math.h>

#define NN   50000
#define EE   800000
#define ETOT (EE + NN)
#define H1N  4
#define C1   256   // H1*64
#define C2   64
#define CAP  128   // per-destination adjacency capacity (deg ~ Poisson(16)+1)

// ---------------- scratch (device globals; no allocations allowed) ----------
__device__ float g_h1[(size_t)NN * C1];    // x @ W1
__device__ float g_out1[(size_t)NN * C1];  // elu(aggregate + b1)  -> layer2 input
__device__ float g_h2[(size_t)NN * C2];    // out1 @ W2
__device__ float g_alsrc1[NN * H1N], g_aldst1[NN * H1N];
__device__ float g_alsrc2[NN],       g_aldst2[NN];
__device__ int   g_cursor[NN];             // degree counters / final degrees
__device__ int   g_csr[(size_t)NN * CAP];  // src lists per destination

// ---------------- init: zero adjacency cursors ------------------------------
__global__ void init_kernel() {
    int tid = blockIdx.x * blockDim.x + threadIdx.x;
    if (tid < NN) g_cursor[tid] = 0;
}

// ---------------- adjacency fill: one pass over edges + self loops ----------
__global__ void fill_adj(const int* __restrict__ ei) {
    int e = blockIdx.x * blockDim.x + threadIdx.x;
    if (e >= ETOT) return;
    int s, d;
    if (e < EE) { s = ei[e]; d = ei[e + EE]; }
    else        { s = d = e - EE; }
    int pos = atomicAdd(&g_cursor[d], 1);
    if (pos < CAP) g_csr[(size_t)d * CAP + pos] = s;
}

// ---------------- tiled fp32 GEMM: C[M,N] = A[M,K] @ B[K,N] -----------------
// 64x64 tile, 256 threads, 4x4 microtile, BK=16. N % 64 == 0, K % 16 == 0.
__global__ void gemm_tiled(const float* __restrict__ A, const float* __restrict__ B,
                           float* __restrict__ C, int M, int K, int N) {
    __shared__ float As[16][64];
    __shared__ float Bs[16][64];
    const int t  = threadIdx.x;
    const int tx = t & 15, ty = t >> 4;
    const int row0 = blockIdx.y * 64, col0 = blockIdx.x * 64;

    float acc[4][4] = {};

    for (int k0 = 0; k0 < K; k0 += 16) {
        int ar = t >> 2, ac = (t & 3) * 4;
        float4 av = make_float4(0.f, 0.f, 0.f, 0.f);
        if (row0 + ar < M)
            av = *(const float4*)&A[(size_t)(row0 + ar) * K + k0 + ac];
        As[ac + 0][ar] = av.x; As[ac + 1][ar] = av.y;
        As[ac + 2][ar] = av.z; As[ac + 3][ar] = av.w;
        int br = t >> 4, bc = (t & 15) * 4;
        *(float4*)&Bs[br][bc] = *(const float4*)&B[(size_t)(k0 + br) * N + col0 + bc];
        __syncthreads();

        #pragma unroll
        for (int kk = 0; kk < 16; kk++) {
            float4 a = *(const float4*)&As[kk][ty * 4];
            float4 b = *(const float4*)&Bs[kk][tx * 4];
            acc[0][0] += a.x * b.x; acc[0][1] += a.x * b.y; acc[0][2] += a.x * b.z; acc[0][3] += a.x * b.w;
            acc[1][0] += a.y * b.x; acc[1][1] += a.y * b.y; acc[1][2] += a.y * b.z; acc[1][3] += a.y * b.w;
            acc[2][0] += a.z * b.x; acc[2][1] += a.z * b.y; acc[2][2] += a.z * b.z; acc[2][3] += a.z * b.w;
            acc[3][0] += a.w * b.x; acc[3][1] += a.w * b.y; acc[3][2] += a.w * b.z; acc[3][3] += a.w * b.w;
        }
        __syncthreads();
    }

    #pragma unroll
    for (int i = 0; i < 4; i++) {
        int r = row0 + ty * 4 + i;
        if (r < M) {
            float4 o = make_float4(acc[i][0], acc[i][1], acc[i][2], acc[i][3]);
            *(float4*)&C[(size_t)r * N + col0 + tx * 4] = o;
        }
    }
}

// ---------------- per-(node, head) attention coefficients -------------------
template <int H>
__global__ void node_al(const float* __restrict__ feat,
                        const float* __restrict__ a_src, const float* __restrict__ a_dst,
                        float* __restrict__ als, float* __restrict__ ald) {
    int tid = blockIdx.x * blockDim.x + threadIdx.x;
    if (tid >= NN * H) return;
    int node = tid / H, h = tid - node * H;
    const float* row = &feat[(size_t)node * (H * 64) + h * 64];
    const float* as  = &a_src[h * 64];
    const float* ad  = &a_dst[h * 64];
    float ss = 0.f, dd = 0.f;
    #pragma unroll
    for (int i = 0; i < 64; i += 4) {
        float4 v  = *(const float4*)&row[i];
        float4 va = *(const float4*)&as[i];
        float4 vb = *(const float4*)&ad[i];
        ss += v.x * va.x + v.y * va.y + v.z * va.z + v.w * va.w;
        dd += v.x * vb.x + v.y * vb.y + v.z * vb.z + v.w * vb.w;
    }
    als[tid] = ss;
    ald[tid] = dd;
}

// ---------------- warp-per-destination softmax + aggregation ----------------
// Loop 1: denominator (no max subtraction; logits are O(10), exp is fp32-safe;
//         softmax ratio is mathematically identical to the max-shifted form).
// Loop 2: alpha * gathered feature row accumulated in registers.
// Epilogue: out = [elu](acc + bias), plain coalesced stores (no atomics).
template <int H, int TC, bool DO_ELU>
__global__ void csr_aggregate(const float* __restrict__ feat,
                              const float* __restrict__ als,
                              const float* __restrict__ ald,
                              const float* __restrict__ bias,
                              float* __restrict__ out) {
    int gw = (blockIdx.x * blockDim.x + threadIdx.x) >> 5;   // destination node
    if (gw >= NN) return;
    const int lane = threadIdx.x & 31;
    constexpr int FPL = TC / 32;                              // 8 (layer1) / 2 (layer2)
    const int col = lane * FPL;
    const int myh = (H == 1) ? 0 : (col >> 6);

    const float aldh = ald[gw * H + myh];
    const int dg = min(g_cursor[gw], CAP);
    const int* lst = &g_csr[(size_t)gw * CAP];

    // pass 1: softmax denominator for my head
    float den = 0.f;
    for (int i = 0; i < dg; i++) {
        int s = lst[i];
        float l = als[s * H + myh] + aldh;
        l = l > 0.f ? l : 0.2f * l;
        den += __expf(l);
    }
    const float rden = 1.f / fmaxf(den, 1e-16f);

    // pass 2: weighted gather-accumulate
    float acc[FPL] = {};
    for (int i = 0; i < dg; i++) {
        int s = lst[i];
        float l = als[s * H + myh] + aldh;
        l = l > 0.f ? l : 0.2f * l;
        float alpha = __expf(l) * rden;
        const float* row = &feat[(size_t)s * TC + col];
        if constexpr (FPL == 8) {
            float4 a = *(const float4*)&row[0];
            float4 b = *(const float4*)&row[4];
            acc[0] += alpha * a.x; acc[1] += alpha * a.y;
            acc[2] += alpha * a.z; acc[3] += alpha * a.w;
            acc[4] += alpha * b.x; acc[5] += alpha * b.y;
            acc[6] += alpha * b.z; acc[7] += alpha * b.w;
        } else {
            float2 a = *(const float2*)&row[0];
            acc[0] += alpha * a.x; acc[1] += alpha * a.y;
        }
    }

    // epilogue: bias (+ elu), vector store
    #pragma unroll
    for (int j = 0; j < FPL; j++) {
        float v = acc[j] + bias[col + j];
        if constexpr (DO_ELU) v = v > 0.f ? v : expm1f(v);
        acc[j] = v;
    }
    float* o = &out[(size_t)gw * TC + col];
    if constexpr (FPL == 8) {
        *(float4*)&o[0] = make_float4(acc[0], acc[1], acc[2], acc[3]);
        *(float4*)&o[4] = make_float4(acc[4], acc[5], acc[6], acc[7]);
    } else {
        *(float2*)&o[0] = make_float2(acc[0], acc[1]);
    }
}

// ---------------- launch ----------------------------------------------------
extern "C" void kernel_launch(void* const* d_in, const int* in_sizes, int n_in,
                              void* d_out, int out_size) {
    (void)n_in; (void)in_sizes; (void)out_size;
    const float* x      = (const float*)d_in[0];
    const int*   ei     = (const int*)d_in[1];   // int32 (JAX default int)
    const float* W1     = (const float*)d_in[2];
    const float* a_src1 = (const float*)d_in[3];
    const float* a_dst1 = (const float*)d_in[4];
    const float* b1     = (const float*)d_in[5];
    const float* W2     = (const float*)d_in[6];
    const float* a_src2 = (const float*)d_in[7];
    const float* a_dst2 = (const float*)d_in[8];
    const float* b2     = (const float*)d_in[9];
    float* dout = (float*)d_out;

    float *h1, *out1, *h2, *alsrc1, *aldst1, *alsrc2, *aldst2;
    cudaGetSymbolAddress((void**)&h1,     g_h1);
    cudaGetSymbolAddress((void**)&out1,   g_out1);
    cudaGetSymbolAddress((void**)&h2,     g_h2);
    cudaGetSymbolAddress((void**)&alsrc1, g_alsrc1);
    cudaGetSymbolAddress((void**)&aldst1, g_aldst1);
    cudaGetSymbolAddress((void**)&alsrc2, g_alsrc2);
    cudaGetSymbolAddress((void**)&aldst2, g_aldst2);

    const int T = 256;
    // 0) adjacency build (shared by both layers)
    init_kernel<<<(NN + T - 1) / T, T>>>();
    fill_adj<<<(ETOT + T - 1) / T, T>>>(ei);
    // 1) h1 = x @ W1
    {
        dim3 g(C1 / 64, (NN + 63) / 64);
        gemm_tiled<<<g, 256>>>(x, W1, h1, NN, 128, C1);
    }
    // 2) attention coefficients, layer 1
    node_al<H1N><<<(NN * H1N + T - 1) / T, T>>>(h1, a_src1, a_dst1, alsrc1, aldst1);
    // 3) fused softmax + aggregate + bias + elu  (layer 1)
    csr_aggregate<H1N, C1, true><<<(NN * 32 + T - 1) / T, T>>>(h1, alsrc1, aldst1, b1, out1);
    // 4) h2 = out1 @ W2
    {
        dim3 g(C2 / 64, (NN + 63) / 64);
        gemm_tiled<<<g, 256>>>(out1, W2, h2, NN, C1, C2);
    }
    // 5) attention coefficients, layer 2
    node_al<1><<<(NN + T - 1) / T, T>>>(h2, a_src2, a_dst2, alsrc2, aldst2);
    // 6) fused softmax + aggregate + bias  (layer 2, straight to d_out)
    csr_aggregate<1, C2, false><<<(NN * 32 + T - 1) / T, T>>>(h2, alsrc2, aldst2, b2, dout);
}

// round 4
// speedup vs baseline: 2.6176x; 1.3157x over previous
#include <cuda_runtime.h>
#include <math.h>

#define NN   50000
#define EE   800000
#define ETOT (EE + NN)
#define H1N  4
#define C1   256   // H1*64
#define C2   64
#define CAP  128   // per-destination adjacency capacity

#define BM 128
#define BN 64
#define BK 16

// ---------------- scratch (device globals; no allocations allowed) ----------
__device__ float g_h1[(size_t)NN * C1];
__device__ float g_out1[(size_t)NN * C1];
__device__ float g_h2[(size_t)NN * C2];
__device__ float g_alsrc1[NN * H1N], g_aldst1[NN * H1N];
__device__ float g_alsrc2[NN],       g_aldst2[NN];
__device__ int   g_cursor[NN];
__device__ int   g_csr[(size_t)NN * CAP];

// ---------------- helpers ----------------------------------------------------
__device__ __forceinline__ float to_tf32(float x) {
    unsigned u;
    asm("cvt.rna.tf32.f32 %0, %1;" : "=r"(u) : "f"(x));
    return __uint_as_float(u);
}
__device__ __forceinline__ void mma_m16n8k8(float* c, const float* a, const float* b) {
    asm volatile("mma.sync.aligned.m16n8k8.row.col.f32.tf32.tf32.f32 "
        "{%0,%1,%2,%3}, {%4,%5,%6,%7}, {%8,%9}, {%0,%1,%2,%3};"
        : "+f"(c[0]), "+f"(c[1]), "+f"(c[2]), "+f"(c[3])
        : "r"(__float_as_uint(a[0])), "r"(__float_as_uint(a[1])),
          "r"(__float_as_uint(a[2])), "r"(__float_as_uint(a[3])),
          "r"(__float_as_uint(b[0])), "r"(__float_as_uint(b[1])));
}

// ---------------- adjacency build -------------------------------------------
__global__ void init_kernel() {
    int tid = blockIdx.x * blockDim.x + threadIdx.x;
    if (tid < NN) g_cursor[tid] = 0;
}
__global__ void fill_adj(const int* __restrict__ ei) {
    int e = blockIdx.x * blockDim.x + threadIdx.x;
    if (e >= ETOT) return;
    int s, d;
    if (e < EE) { s = ei[e]; d = ei[e + EE]; }
    else        { s = d = e - EE; }
    int pos = atomicAdd(&g_cursor[d], 1);
    if (pos < CAP) g_csr[(size_t)d * CAP + pos] = s;
}

// ---------------- tf32 mma GEMM + fused attention-coefficient epilogue ------
// C[M,N_] = A[M,K] @ B[K,N_], one 64-col block per head (blockIdx.x = head).
// Epilogue: als[row*H+head] = sum_col C*asrc[head*64+col], same for ald.
template <int H>
__global__ __launch_bounds__(256, 2)
void gemm_mma_al(const float* __restrict__ A, const float* __restrict__ B,
                 float* __restrict__ C,
                 const float* __restrict__ asrc, const float* __restrict__ adst,
                 float* __restrict__ als, float* __restrict__ ald,
                 int M, int K, int N_) {
    __shared__ float As[BK][BM + 4];   // stride 132: conflict-free frag loads
    __shared__ float Bs[BK][BN + 4];   // stride 68
    __shared__ float red_s[2][BM], red_d[2][BM];

    const int t    = threadIdx.x;
    const int lane = t & 31, wid = t >> 5;
    const int wm = wid & 3, wn = wid >> 2;      // 4x2 warp grid
    const int grp = lane >> 2, tig = lane & 3;
    const int head = blockIdx.x;
    const int row0 = blockIdx.y * BM;
    const int col0 = head * BN;

    float acc[2][4][4] = {};

    for (int k0 = 0; k0 < K; k0 += BK) {
        // ---- stage A (transposed, tf32-rounded) ----
        #pragma unroll
        for (int it = 0; it < 2; it++) {
            int idx = it * 256 + t;
            int rl = idx >> 2, c4 = (idx & 3) * 4;
            int gr = row0 + rl;
            float4 v = make_float4(0.f, 0.f, 0.f, 0.f);
            if (gr < M) v = *(const float4*)&A[(size_t)gr * K + k0 + c4];
            As[c4 + 0][rl] = to_tf32(v.x); As[c4 + 1][rl] = to_tf32(v.y);
            As[c4 + 2][rl] = to_tf32(v.z); As[c4 + 3][rl] = to_tf32(v.w);
        }
        // ---- stage B (tf32-rounded) ----
        {
            int rl = t >> 4, c4 = (t & 15) * 4;
            float4 v = *(const float4*)&B[(size_t)(k0 + rl) * N_ + col0 + c4];
            float4 w = make_float4(to_tf32(v.x), to_tf32(v.y), to_tf32(v.z), to_tf32(v.w));
            *(float4*)&Bs[rl][c4] = w;
        }
        __syncthreads();

        #pragma unroll
        for (int kk = 0; kk < BK; kk += 8) {
            float a[2][4], b[4][2];
            #pragma unroll
            for (int mt = 0; mt < 2; mt++) {
                int m0 = wm * 32 + mt * 16;
                a[mt][0] = As[kk + tig][m0 + grp];
                a[mt][1] = As[kk + tig][m0 + grp + 8];
                a[mt][2] = As[kk + tig + 4][m0 + grp];
                a[mt][3] = As[kk + tig + 4][m0 + grp + 8];
            }
            #pragma unroll
            for (int nt = 0; nt < 4; nt++) {
                int n0 = wn * 32 + nt * 8;
                b[nt][0] = Bs[kk + tig][n0 + grp];
                b[nt][1] = Bs[kk + tig + 4][n0 + grp];
            }
            #pragma unroll
            for (int mt = 0; mt < 2; mt++)
                #pragma unroll
                for (int nt = 0; nt < 4; nt++)
                    mma_m16n8k8(acc[mt][nt], a[mt], b[nt]);
        }
        __syncthreads();
    }

    // ---- epilogue: store C + fused al_src/al_dst dots ----
    float ps[2][2] = {}, pd[2][2] = {};
    #pragma unroll
    for (int mt = 0; mt < 2; mt++) {
        int r0 = row0 + wm * 32 + mt * 16 + grp;
        #pragma unroll
        for (int nt = 0; nt < 4; nt++) {
            int cih = wn * 32 + nt * 8 + tig * 2;   // col within head
            float c0 = acc[mt][nt][0], c1 = acc[mt][nt][1];
            float c2 = acc[mt][nt][2], c3 = acc[mt][nt][3];
            if (r0 < M)     *(float2*)&C[(size_t)r0 * N_ + col0 + cih]       = make_float2(c0, c1);
            if (r0 + 8 < M) *(float2*)&C[(size_t)(r0 + 8) * N_ + col0 + cih] = make_float2(c2, c3);
            float as0 = asrc[head * 64 + cih], as1 = asrc[head * 64 + cih + 1];
            float ad0 = adst[head * 64 + cih], ad1 = adst[head * 64 + cih + 1];
            ps[mt][0] += c0 * as0 + c1 * as1;  ps[mt][1] += c2 * as0 + c3 * as1;
            pd[mt][0] += c0 * ad0 + c1 * ad1;  pd[mt][1] += c2 * ad0 + c3 * ad1;
        }
    }
    // reduce over the quad (tig)
    #pragma unroll
    for (int mt = 0; mt < 2; mt++)
        #pragma unroll
        for (int rh = 0; rh < 2; rh++) {
            float s = ps[mt][rh], d = pd[mt][rh];
            s += __shfl_xor_sync(0xffffffffu, s, 1);
            s += __shfl_xor_sync(0xffffffffu, s, 2);
            d += __shfl_xor_sync(0xffffffffu, d, 1);
            d += __shfl_xor_sync(0xffffffffu, d, 2);
            if (tig == 0) {
                int rloc = wm * 32 + mt * 16 + rh * 8 + grp;
                red_s[wn][rloc] = s;
                red_d[wn][rloc] = d;
            }
        }
    __syncthreads();
    if (t < BM) {
        int row = row0 + t;
        if (row < M) {
            als[(size_t)row * H + head] = red_s[0][t] + red_s[1][t];
            ald[(size_t)row * H + head] = red_d[0][t] + red_d[1][t];
        }
    }
}

// ---------------- warp-per-destination softmax + aggregation ----------------
template <int H, int TC, bool DO_ELU>
__global__ void csr_aggregate(const float* __restrict__ feat,
                              const float* __restrict__ als,
                              const float* __restrict__ ald,
                              const float* __restrict__ bias,
                              float* __restrict__ out) {
    int gw = (blockIdx.x * blockDim.x + threadIdx.x) >> 5;   // destination node
    if (gw >= NN) return;
    const int lane = threadIdx.x & 31;
    constexpr int FPL = TC / 32;                              // 8 / 2
    const int col = lane * FPL;
    const int myh = (H == 1) ? 0 : (col >> 6);

    const float aldh = ald[gw * H + myh];
    const int dg = min(g_cursor[gw], CAP);
    const int* lst = &g_csr[(size_t)gw * CAP];

    float den = 0.f;
    for (int i = 0; i < dg; i++) {
        int s = lst[i];
        float l = als[s * H + myh] + aldh;
        l = l > 0.f ? l : 0.2f * l;
        den += __expf(l);
    }
    const float rden = 1.f / fmaxf(den, 1e-16f);

    float acc[FPL] = {};
    for (int i = 0; i < dg; i++) {
        int s = lst[i];
        float l = als[s * H + myh] + aldh;
        l = l > 0.f ? l : 0.2f * l;
        float alpha = __expf(l) * rden;
        const float* row = &feat[(size_t)s * TC + col];
        if constexpr (FPL == 8) {
            float4 a = *(const float4*)&row[0];
            float4 b = *(const float4*)&row[4];
            acc[0] += alpha * a.x; acc[1] += alpha * a.y;
            acc[2] += alpha * a.z; acc[3] += alpha * a.w;
            acc[4] += alpha * b.x; acc[5] += alpha * b.y;
            acc[6] += alpha * b.z; acc[7] += alpha * b.w;
        } else {
            float2 a = *(const float2*)&row[0];
            acc[0] += alpha * a.x; acc[1] += alpha * a.y;
        }
    }

    #pragma unroll
    for (int j = 0; j < FPL; j++) {
        float v = acc[j] + bias[col + j];
        if constexpr (DO_ELU) v = v > 0.f ? v : expm1f(v);
        acc[j] = v;
    }
    float* o = &out[(size_t)gw * TC + col];
    if constexpr (FPL == 8) {
        *(float4*)&o[0] = make_float4(acc[0], acc[1], acc[2], acc[3]);
        *(float4*)&o[4] = make_float4(acc[4], acc[5], acc[6], acc[7]);
    } else {
        *(float2*)&o[0] = make_float2(acc[0], acc[1]);
    }
}

// ---------------- launch -----------------------------------------------------
extern "C" void kernel_launch(void* const* d_in, const int* in_sizes, int n_in,
                              void* d_out, int out_size) {
    (void)n_in; (void)in_sizes; (void)out_size;
    const float* x      = (const float*)d_in[0];
    const int*   ei     = (const int*)d_in[1];
    const float* W1     = (const float*)d_in[2];
    const float* a_src1 = (const float*)d_in[3];
    const float* a_dst1 = (const float*)d_in[4];
    const float* b1     = (const float*)d_in[5];
    const float* W2     = (const float*)d_in[6];
    const float* a_src2 = (const float*)d_in[7];
    const float* a_dst2 = (const float*)d_in[8];
    const float* b2     = (const float*)d_in[9];
    float* dout = (float*)d_out;

    float *h1, *out1, *h2, *alsrc1, *aldst1, *alsrc2, *aldst2;
    cudaGetSymbolAddress((void**)&h1,     g_h1);
    cudaGetSymbolAddress((void**)&out1,   g_out1);
    cudaGetSymbolAddress((void**)&h2,     g_h2);
    cudaGetSymbolAddress((void**)&alsrc1, g_alsrc1);
    cudaGetSymbolAddress((void**)&aldst1, g_aldst1);
    cudaGetSymbolAddress((void**)&alsrc2, g_alsrc2);
    cudaGetSymbolAddress((void**)&aldst2, g_aldst2);

    const int T = 256;
    // 0) adjacency build (shared by both layers)
    init_kernel<<<(NN + T - 1) / T, T>>>();
    fill_adj<<<(ETOT + T - 1) / T, T>>>(ei);
    // 1) h1 = x @ W1 (+ als1/ald1 fused)
    {
        dim3 g(C1 / BN, (NN + BM - 1) / BM);
        gemm_mma_al<H1N><<<g, 256>>>(x, W1, h1, a_src1, a_dst1,
                                     alsrc1, aldst1, NN, 128, C1);
    }
    // 2) fused softmax + aggregate + bias + elu  (layer 1)
    csr_aggregate<H1N, C1, true><<<(NN * 32 + T - 1) / T, T>>>(h1, alsrc1, aldst1, b1, out1);
    // 3) h2 = out1 @ W2 (+ als2/ald2 fused)
    {
        dim3 g(C2 / BN, (NN + BM - 1) / BM);
        gemm_mma_al<1><<<g, 256>>>(out1, W2, h2, a_src2, a_dst2,
                                   alsrc2, aldst2, NN, C1, C2);
    }
    // 4) fused softmax + aggregate + bias  (layer 2, straight to d_out)
    csr_aggregate<1, C2, false><<<(NN * 32 + T - 1) / T, T>>>(h2, alsrc2, aldst2, b2, dout);
}

// round 5
// speedup vs baseline: 2.7306x; 1.0432x over previous
#include <cuda_runtime.h>
#include <math.h>

#define NN   50000
#define EE   800000
#define ETOT (EE + NN)
#define H1N  4
#define C1   256   // H1*64
#define C2   64
#define CAP  128   // per-destination adjacency capacity

#define BM 128
#define BN 64
#define BK 16

// ---------------- scratch (device globals; no allocations allowed) ----------
__device__ float g_h1[(size_t)NN * C1];
__device__ float g_out1[(size_t)NN * C1];
__device__ float g_h2[(size_t)NN * C2];
__device__ float g_alsrc1[NN * H1N], g_aldst1[NN * H1N];
__device__ float g_alsrc2[NN],       g_aldst2[NN];
__device__ int   g_cursor[NN];
__device__ int   g_csr[(size_t)NN * CAP];

// ---------------- helpers ----------------------------------------------------
__device__ __forceinline__ float to_tf32(float x) {
    unsigned u;
    asm("cvt.rna.tf32.f32 %0, %1;" : "=r"(u) : "f"(x));
    return __uint_as_float(u);
}
__device__ __forceinline__ void mma_m16n8k8(float* c, const float* a, const float* b) {
    asm volatile("mma.sync.aligned.m16n8k8.row.col.f32.tf32.tf32.f32 "
        "{%0,%1,%2,%3}, {%4,%5,%6,%7}, {%8,%9}, {%0,%1,%2,%3};"
        : "+f"(c[0]), "+f"(c[1]), "+f"(c[2]), "+f"(c[3])
        : "r"(__float_as_uint(a[0])), "r"(__float_as_uint(a[1])),
          "r"(__float_as_uint(a[2])), "r"(__float_as_uint(a[3])),
          "r"(__float_as_uint(b[0])), "r"(__float_as_uint(b[1])));
}

// ---------------- adjacency build -------------------------------------------
__global__ void init_kernel() {
    int tid = blockIdx.x * blockDim.x + threadIdx.x;
    if (tid < NN) g_cursor[tid] = 0;
}
__global__ void fill_adj(const int* __restrict__ ei) {
    int e = blockIdx.x * blockDim.x + threadIdx.x;
    if (e >= ETOT) return;
    int s, d;
    if (e < EE) { s = ei[e]; d = ei[e + EE]; }
    else        { s = d = e - EE; }
    int pos = atomicAdd(&g_cursor[d], 1);
    if (pos < CAP) g_csr[(size_t)d * CAP + pos] = s;
}

// ---------------- tf32 mma GEMM + fused attention-coefficient epilogue ------
template <int H>
__global__ __launch_bounds__(256, 2)
void gemm_mma_al(const float* __restrict__ A, const float* __restrict__ B,
                 float* __restrict__ C,
                 const float* __restrict__ asrc, const float* __restrict__ adst,
                 float* __restrict__ als, float* __restrict__ ald,
                 int M, int K, int N_) {
    __shared__ float As[BK][BM + 4];
    __shared__ float Bs[BK][BN + 4];
    __shared__ float red_s[2][BM], red_d[2][BM];

    const int t    = threadIdx.x;
    const int lane = t & 31, wid = t >> 5;
    const int wm = wid & 3, wn = wid >> 2;      // 4x2 warp grid
    const int grp = lane >> 2, tig = lane & 3;
    const int head = blockIdx.x;
    const int row0 = blockIdx.y * BM;
    const int col0 = head * BN;

    float acc[2][4][4] = {};

    for (int k0 = 0; k0 < K; k0 += BK) {
        #pragma unroll
        for (int it = 0; it < 2; it++) {
            int idx = it * 256 + t;
            int rl = idx >> 2, c4 = (idx & 3) * 4;
            int gr = row0 + rl;
            float4 v = make_float4(0.f, 0.f, 0.f, 0.f);
            if (gr < M) v = *(const float4*)&A[(size_t)gr * K + k0 + c4];
            As[c4 + 0][rl] = to_tf32(v.x); As[c4 + 1][rl] = to_tf32(v.y);
            As[c4 + 2][rl] = to_tf32(v.z); As[c4 + 3][rl] = to_tf32(v.w);
        }
        {
            int rl = t >> 4, c4 = (t & 15) * 4;
            float4 v = *(const float4*)&B[(size_t)(k0 + rl) * N_ + col0 + c4];
            float4 w = make_float4(to_tf32(v.x), to_tf32(v.y), to_tf32(v.z), to_tf32(v.w));
            *(float4*)&Bs[rl][c4] = w;
        }
        __syncthreads();

        #pragma unroll
        for (int kk = 0; kk < BK; kk += 8) {
            float a[2][4], b[4][2];
            #pragma unroll
            for (int mt = 0; mt < 2; mt++) {
                int m0 = wm * 32 + mt * 16;
                a[mt][0] = As[kk + tig][m0 + grp];
                a[mt][1] = As[kk + tig][m0 + grp + 8];
                a[mt][2] = As[kk + tig + 4][m0 + grp];
                a[mt][3] = As[kk + tig + 4][m0 + grp + 8];
            }
            #pragma unroll
            for (int nt = 0; nt < 4; nt++) {
                int n0 = wn * 32 + nt * 8;
                b[nt][0] = Bs[kk + tig][n0 + grp];
                b[nt][1] = Bs[kk + tig + 4][n0 + grp];
            }
            #pragma unroll
            for (int mt = 0; mt < 2; mt++)
                #pragma unroll
                for (int nt = 0; nt < 4; nt++)
                    mma_m16n8k8(acc[mt][nt], a[mt], b[nt]);
        }
        __syncthreads();
    }

    float ps[2][2] = {}, pd[2][2] = {};
    #pragma unroll
    for (int mt = 0; mt < 2; mt++) {
        int r0 = row0 + wm * 32 + mt * 16 + grp;
        #pragma unroll
        for (int nt = 0; nt < 4; nt++) {
            int cih = wn * 32 + nt * 8 + tig * 2;
            float c0 = acc[mt][nt][0], c1 = acc[mt][nt][1];
            float c2 = acc[mt][nt][2], c3 = acc[mt][nt][3];
            if (r0 < M)     *(float2*)&C[(size_t)r0 * N_ + col0 + cih]       = make_float2(c0, c1);
            if (r0 + 8 < M) *(float2*)&C[(size_t)(r0 + 8) * N_ + col0 + cih] = make_float2(c2, c3);
            float as0 = asrc[head * 64 + cih], as1 = asrc[head * 64 + cih + 1];
            float ad0 = adst[head * 64 + cih], ad1 = adst[head * 64 + cih + 1];
            ps[mt][0] += c0 * as0 + c1 * as1;  ps[mt][1] += c2 * as0 + c3 * as1;
            pd[mt][0] += c0 * ad0 + c1 * ad1;  pd[mt][1] += c2 * ad0 + c3 * ad1;
        }
    }
    #pragma unroll
    for (int mt = 0; mt < 2; mt++)
        #pragma unroll
        for (int rh = 0; rh < 2; rh++) {
            float s = ps[mt][rh], d = pd[mt][rh];
            s += __shfl_xor_sync(0xffffffffu, s, 1);
            s += __shfl_xor_sync(0xffffffffu, s, 2);
            d += __shfl_xor_sync(0xffffffffu, d, 1);
            d += __shfl_xor_sync(0xffffffffu, d, 2);
            if (tig == 0) {
                int rloc = wm * 32 + mt * 16 + rh * 8 + grp;
                red_s[wn][rloc] = s;
                red_d[wn][rloc] = d;
            }
        }
    __syncthreads();
    if (t < BM) {
        int row = row0 + t;
        if (row < M) {
            als[(size_t)row * H + head] = red_s[0][t] + red_s[1][t];
            ald[(size_t)row * H + head] = red_d[0][t] + red_d[1][t];
        }
    }
}

// ---------------- warp-per-destination softmax + aggregation ----------------
// Pass 1 (flattened over lanes): each (edge, head) exp computed exactly once,
// cached in smem; denominator via xor-shuffle reduction.
// Pass 2: whole warp walks edges together; lane loads float2 at col
// j*64 + lane*2 (head == j) -> each LDG.64 spans 2 cache lines (no 8-line
// replay bursts), alphas come from one broadcast LDS per edge.
template <int H, int TC, bool DO_ELU>
__global__ __launch_bounds__(256)
void csr_aggregate(const float* __restrict__ feat,
                   const float* __restrict__ als,
                   const float* __restrict__ ald,
                   const float* __restrict__ bias,
                   float* __restrict__ out) {
    __shared__ float sm_exp[8][CAP * H];
    const int w    = threadIdx.x >> 5;
    const int lane = threadIdx.x & 31;
    int gw = (blockIdx.x * blockDim.x + threadIdx.x) >> 5;   // destination node
    if (gw >= NN) return;

    const int dg = min(g_cursor[gw], CAP);
    const int* lst = &g_csr[(size_t)gw * CAP];

    // ---- pass 1: exp of leaky-relu logits, once per (edge, head) ----
    const int hl = (H == 1) ? 0 : (lane & (H - 1));
    const float aldh = ald[gw * H + hl];
    float denp = 0.f;
    for (int base = 0; base < dg * H; base += 32) {
        int idx = base + lane;
        if (idx < dg * H) {
            int i = (H == 1) ? idx : (idx >> 2);
            int s = lst[i];
            float l = als[s * H + hl] + aldh;
            l = l > 0.f ? l : 0.2f * l;
            float e = __expf(l);
            sm_exp[w][idx] = e;
            denp += e;
        }
    }
    #pragma unroll
    for (int off = H; off < 32; off <<= 1)
        denp += __shfl_xor_sync(0xffffffffu, denp, off);
    float rden[H];
    #pragma unroll
    for (int h = 0; h < H; h++)
        rden[h] = 1.f / fmaxf(__shfl_sync(0xffffffffu, denp, h), 1e-16f);
    __syncwarp();

    // ---- pass 2: weighted gather-accumulate, coalesced float2 lanes ----
    constexpr int J = TC / 64;          // 4 (layer1) / 1 (layer2)
    float2 acc[J];
    #pragma unroll
    for (int j = 0; j < J; j++) acc[j] = make_float2(0.f, 0.f);

    for (int i = 0; i < dg; i++) {
        int s = lst[i];
        float al[J];
        if constexpr (H == 4) {
            float4 e4 = *(const float4*)&sm_exp[w][i * 4];
            al[0] = e4.x * rden[0]; al[1] = e4.y * rden[1];
            al[2] = e4.z * rden[2]; al[3] = e4.w * rden[3];
        } else {
            al[0] = sm_exp[w][i] * rden[0];
        }
        const float* row = &feat[(size_t)s * TC + lane * 2];
        #pragma unroll
        for (int j = 0; j < J; j++) {
            float2 v = *(const float2*)&row[j * 64];
            acc[j].x += al[j] * v.x;
            acc[j].y += al[j] * v.y;
        }
    }

    // ---- epilogue: bias (+ elu), coalesced float2 stores ----
    #pragma unroll
    for (int j = 0; j < J; j++) {
        int col = j * 64 + lane * 2;
        float vx = acc[j].x + bias[col];
        float vy = acc[j].y + bias[col + 1];
        if constexpr (DO_ELU) {
            vx = vx > 0.f ? vx : expm1f(vx);
            vy = vy > 0.f ? vy : expm1f(vy);
        }
        *(float2*)&out[(size_t)gw * TC + col] = make_float2(vx, vy);
    }
}

// ---------------- launch -----------------------------------------------------
extern "C" void kernel_launch(void* const* d_in, const int* in_sizes, int n_in,
                              void* d_out, int out_size) {
    (void)n_in; (void)in_sizes; (void)out_size;
    const float* x      = (const float*)d_in[0];
    const int*   ei     = (const int*)d_in[1];
    const float* W1     = (const float*)d_in[2];
    const float* a_src1 = (const float*)d_in[3];
    const float* a_dst1 = (const float*)d_in[4];
    const float* b1     = (const float*)d_in[5];
    const float* W2     = (const float*)d_in[6];
    const float* a_src2 = (const float*)d_in[7];
    const float* a_dst2 = (const float*)d_in[8];
    const float* b2     = (const float*)d_in[9];
    float* dout = (float*)d_out;

    float *h1, *out1, *h2, *alsrc1, *aldst1, *alsrc2, *aldst2;
    cudaGetSymbolAddress((void**)&h1,     g_h1);
    cudaGetSymbolAddress((void**)&out1,   g_out1);
    cudaGetSymbolAddress((void**)&h2,     g_h2);
    cudaGetSymbolAddress((void**)&alsrc1, g_alsrc1);
    cudaGetSymbolAddress((void**)&aldst1, g_aldst1);
    cudaGetSymbolAddress((void**)&alsrc2, g_alsrc2);
    cudaGetSymbolAddress((void**)&aldst2, g_aldst2);

    const int T = 256;
    // 0) adjacency build (shared by both layers)
    init_kernel<<<(NN + T - 1) / T, T>>>();
    fill_adj<<<(ETOT + T - 1) / T, T>>>(ei);
    // 1) h1 = x @ W1 (+ als1/ald1 fused)
    {
        dim3 g(C1 / BN, (NN + BM - 1) / BM);
        gemm_mma_al<H1N><<<g, 256>>>(x, W1, h1, a_src1, a_dst1,
                                     alsrc1, aldst1, NN, 128, C1);
    }
    // 2) fused softmax + aggregate + bias + elu  (layer 1)
    csr_aggregate<H1N, C1, true><<<(NN * 32 + T - 1) / T, T>>>(h1, alsrc1, aldst1, b1, out1);
    // 3) h2 = out1 @ W2 (+ als2/ald2 fused)
    {
        dim3 g(C2 / BN, (NN + BM - 1) / BM);
        gemm_mma_al<1><<<g, 256>>>(out1, W2, h2, a_src2, a_dst2,
                                   alsrc2, aldst2, NN, C1, C2);
    }
    // 4) fused softmax + aggregate + bias  (layer 2, straight to d_out)
    csr_aggregate<1, C2, false><<<(NN * 32 + T - 1) / T, T>>>(h2, alsrc2, aldst2, b2, dout);
}

// round 6
// speedup vs baseline: 2.8106x; 1.0293x over previous
#include <cuda_runtime.h>
#include <cuda_fp16.h>
#include <math.h>

#define NN   50000
#define EE   800000
#define ETOT (EE + NN)
#define H1N  4
#define C1   256   // H1*64
#define C2   64
#define CAP  128   // per-destination adjacency capacity

#define BM 128
#define BN 64
#define BK 16

// ---------------- scratch (device globals; no allocations allowed) ----------
__device__ __half g_h1[(size_t)NN * C1];
__device__ __half g_out1[(size_t)NN * C1];
__device__ __half g_h2[(size_t)NN * C2];
__device__ float  g_alsrc1[NN * H1N], g_aldst1[NN * H1N];
__device__ float  g_alsrc2[NN],       g_aldst2[NN];
__device__ int    g_cursor[NN];
__device__ int    g_csr[(size_t)NN * CAP];

// ---------------- helpers ----------------------------------------------------
__device__ __forceinline__ float to_tf32(float x) {
    unsigned u;
    asm("cvt.rna.tf32.f32 %0, %1;" : "=r"(u) : "f"(x));
    return __uint_as_float(u);
}
__device__ __forceinline__ void mma_m16n8k8(float* c, const float* a, const float* b) {
    asm volatile("mma.sync.aligned.m16n8k8.row.col.f32.tf32.tf32.f32 "
        "{%0,%1,%2,%3}, {%4,%5,%6,%7}, {%8,%9}, {%0,%1,%2,%3};"
        : "+f"(c[0]), "+f"(c[1]), "+f"(c[2]), "+f"(c[3])
        : "r"(__float_as_uint(a[0])), "r"(__float_as_uint(a[1])),
          "r"(__float_as_uint(a[2])), "r"(__float_as_uint(a[3])),
          "r"(__float_as_uint(b[0])), "r"(__float_as_uint(b[1])));
}

// ---------------- adjacency build -------------------------------------------
__global__ void init_kernel() {
    int tid = blockIdx.x * blockDim.x + threadIdx.x;
    if (tid < NN) g_cursor[tid] = 0;
}
__global__ void fill_adj(const int* __restrict__ ei) {
    int e = blockIdx.x * blockDim.x + threadIdx.x;
    if (e >= ETOT) return;
    int s, d;
    if (e < EE) { s = ei[e]; d = ei[e + EE]; }
    else        { s = d = e - EE; }
    int pos = atomicAdd(&g_cursor[d], 1);
    if (pos < CAP) g_csr[(size_t)d * CAP + pos] = s;
}

// ---------------- tf32 mma GEMM + fused attention-coefficient epilogue ------
// A fp32 or fp16 (templated); C stored fp16; al dots from fp32 accumulators.
template <int H, typename AT>
__global__ __launch_bounds__(256, 2)
void gemm_mma_al(const AT* __restrict__ A, const float* __restrict__ B,
                 __half* __restrict__ C,
                 const float* __restrict__ asrc, const float* __restrict__ adst,
                 float* __restrict__ als, float* __restrict__ ald,
                 int M, int K, int N_) {
    __shared__ float As[BK][BM + 4];
    __shared__ float Bs[BK][BN + 4];
    __shared__ float red_s[2][BM], red_d[2][BM];

    const int t    = threadIdx.x;
    const int lane = t & 31, wid = t >> 5;
    const int wm = wid & 3, wn = wid >> 2;      // 4x2 warp grid
    const int grp = lane >> 2, tig = lane & 3;
    const int head = blockIdx.x;
    const int row0 = blockIdx.y * BM;
    const int col0 = head * BN;

    float acc[2][4][4] = {};

    for (int k0 = 0; k0 < K; k0 += BK) {
        // ---- stage A (transposed, tf32-rounded) ----
        if constexpr (sizeof(AT) == 4) {
            #pragma unroll
            for (int it = 0; it < 2; it++) {
                int idx = it * 256 + t;
                int rl = idx >> 2, c4 = (idx & 3) * 4;
                int gr = row0 + rl;
                float4 v = make_float4(0.f, 0.f, 0.f, 0.f);
                if (gr < M) v = *(const float4*)&A[(size_t)gr * K + k0 + c4];
                As[c4 + 0][rl] = to_tf32(v.x); As[c4 + 1][rl] = to_tf32(v.y);
                As[c4 + 2][rl] = to_tf32(v.z); As[c4 + 3][rl] = to_tf32(v.w);
            }
        } else {
            // fp16 A: 256 threads, each loads 8 halves (16B); fp16 c tf32 (exact)
            int rl = t >> 1, c8 = (t & 1) * 8;
            int gr = row0 + rl;
            uint4 u = make_uint4(0u, 0u, 0u, 0u);
            if (gr < M) u = *(const uint4*)&A[(size_t)gr * K + k0 + c8];
            const __half2* hp = (const __half2*)&u;
            #pragma unroll
            for (int j = 0; j < 4; j++) {
                float2 f = __half22float2(hp[j]);
                As[c8 + j * 2 + 0][rl] = f.x;
                As[c8 + j * 2 + 1][rl] = f.y;
            }
        }
        // ---- stage B (tf32-rounded) ----
        {
            int rl = t >> 4, c4 = (t & 15) * 4;
            float4 v = *(const float4*)&B[(size_t)(k0 + rl) * N_ + col0 + c4];
            *(float4*)&Bs[rl][c4] = make_float4(to_tf32(v.x), to_tf32(v.y),
                                                to_tf32(v.z), to_tf32(v.w));
        }
        __syncthreads();

        #pragma unroll
        for (int kk = 0; kk < BK; kk += 8) {
            float a[2][4], b[4][2];
            #pragma unroll
            for (int mt = 0; mt < 2; mt++) {
                int m0 = wm * 32 + mt * 16;
                a[mt][0] = As[kk + tig][m0 + grp];
                a[mt][1] = As[kk + tig][m0 + grp + 8];
                a[mt][2] = As[kk + tig + 4][m0 + grp];
                a[mt][3] = As[kk + tig + 4][m0 + grp + 8];
            }
            #pragma unroll
            for (int nt = 0; nt < 4; nt++) {
                int n0 = wn * 32 + nt * 8;
                b[nt][0] = Bs[kk + tig][n0 + grp];
                b[nt][1] = Bs[kk + tig + 4][n0 + grp];
            }
            #pragma unroll
            for (int mt = 0; mt < 2; mt++)
                #pragma unroll
                for (int nt = 0; nt < 4; nt++)
                    mma_m16n8k8(acc[mt][nt], a[mt], b[nt]);
        }
        __syncthreads();
    }

    // ---- epilogue: fp16 store + fused al_src/al_dst dots (fp32) ----
    float ps[2][2] = {}, pd[2][2] = {};
    #pragma unroll
    for (int mt = 0; mt < 2; mt++) {
        int r0 = row0 + wm * 32 + mt * 16 + grp;
        #pragma unroll
        for (int nt = 0; nt < 4; nt++) {
            int cih = wn * 32 + nt * 8 + tig * 2;
            float c0 = acc[mt][nt][0], c1 = acc[mt][nt][1];
            float c2 = acc[mt][nt][2], c3 = acc[mt][nt][3];
            if (r0 < M)
                *(__half2*)&C[(size_t)r0 * N_ + col0 + cih] = __floats2half2_rn(c0, c1);
            if (r0 + 8 < M)
                *(__half2*)&C[(size_t)(r0 + 8) * N_ + col0 + cih] = __floats2half2_rn(c2, c3);
            float as0 = asrc[head * 64 + cih], as1 = asrc[head * 64 + cih + 1];
            float ad0 = adst[head * 64 + cih], ad1 = adst[head * 64 + cih + 1];
            ps[mt][0] += c0 * as0 + c1 * as1;  ps[mt][1] += c2 * as0 + c3 * as1;
            pd[mt][0] += c0 * ad0 + c1 * ad1;  pd[mt][1] += c2 * ad0 + c3 * ad1;
        }
    }
    #pragma unroll
    for (int mt = 0; mt < 2; mt++)
        #pragma unroll
        for (int rh = 0; rh < 2; rh++) {
            float s = ps[mt][rh], d = pd[mt][rh];
            s += __shfl_xor_sync(0xffffffffu, s, 1);
            s += __shfl_xor_sync(0xffffffffu, s, 2);
            d += __shfl_xor_sync(0xffffffffu, d, 1);
            d += __shfl_xor_sync(0xffffffffu, d, 2);
            if (tig == 0) {
                int rloc = wm * 32 + mt * 16 + rh * 8 + grp;
                red_s[wn][rloc] = s;
                red_d[wn][rloc] = d;
            }
        }
    __syncthreads();
    if (t < BM) {
        int row = row0 + t;
        if (row < M) {
            als[(size_t)row * H + head] = red_s[0][t] + red_s[1][t];
            ald[(size_t)row * H + head] = red_d[0][t] + red_d[1][t];
        }
    }
}

// ---------------- warp-per-destination softmax + aggregation (fp16 feat) ----
// R4 loop shape (fastest measured), traffic halved by half-precision features.
// Layer1: lane covers 8 halves -> one LDG.128 per warp-edge (4 L1 wavefronts).
// Layer2: lane covers 2 halves -> one LDG.32, warp-edge = 1 cache line.
template <int H, int TC, bool DO_ELU, typename OutT>
__global__ __launch_bounds__(256)
void csr_aggregate(const __half* __restrict__ feat,
                   const float* __restrict__ als,
                   const float* __restrict__ ald,
                   const float* __restrict__ bias,
                   OutT* __restrict__ out) {
    int gw = (blockIdx.x * blockDim.x + threadIdx.x) >> 5;   // destination node
    if (gw >= NN) return;
    const int lane = threadIdx.x & 31;
    constexpr int FPL = TC / 32;                              // 8 / 2 halves per lane
    const int col = lane * FPL;
    const int myh = (H == 1) ? 0 : (col >> 6);

    const float aldh = ald[gw * H + myh];
    const int dg = min(g_cursor[gw], CAP);
    const int* lst = &g_csr[(size_t)gw * CAP];

    // pass 1: softmax denominator for my head
    float den = 0.f;
    for (int i = 0; i < dg; i++) {
        int s = lst[i];
        float l = als[s * H + myh] + aldh;
        l = l > 0.f ? l : 0.2f * l;
        den += __expf(l);
    }
    const float rden = 1.f / fmaxf(den, 1e-16f);

    // pass 2: weighted gather-accumulate (fp32 accumulators)
    float acc[FPL] = {};
    for (int i = 0; i < dg; i++) {
        int s = lst[i];
        float l = als[s * H + myh] + aldh;
        l = l > 0.f ? l : 0.2f * l;
        float alpha = __expf(l) * rden;
        const __half* row = &feat[(size_t)s * TC + col];
        if constexpr (FPL == 8) {
            uint4 u = *(const uint4*)row;
            const __half2* hp = (const __half2*)&u;
            #pragma unroll
            for (int j = 0; j < 4; j++) {
                float2 f = __half22float2(hp[j]);
                acc[j * 2 + 0] += alpha * f.x;
                acc[j * 2 + 1] += alpha * f.y;
            }
        } else {
            float2 f = __half22float2(*(const __half2*)row);
            acc[0] += alpha * f.x;
            acc[1] += alpha * f.y;
        }
    }

    // epilogue: bias (+ elu), store half (layer1) or float (final output)
    #pragma unroll
    for (int j = 0; j < FPL; j++) {
        float v = acc[j] + bias[col + j];
        if constexpr (DO_ELU) v = v > 0.f ? v : expm1f(v);
        acc[j] = v;
    }
    if constexpr (sizeof(OutT) == 2) {
        __half2 hv[FPL / 2];
        #pragma unroll
        for (int j = 0; j < FPL / 2; j++)
            hv[j] = __floats2half2_rn(acc[j * 2], acc[j * 2 + 1]);
        if constexpr (FPL == 8)
            *(uint4*)&out[(size_t)gw * TC + col] = *(uint4*)hv;
        else
            *(__half2*)&out[(size_t)gw * TC + col] = hv[0];
    } else {
        if constexpr (FPL == 8) {
            *(float4*)&out[(size_t)gw * TC + col]     = make_float4(acc[0], acc[1], acc[2], acc[3]);
            *(float4*)&out[(size_t)gw * TC + col + 4] = make_float4(acc[4], acc[5], acc[6], acc[7]);
        } else {
            *(float2*)&out[(size_t)gw * TC + col] = make_float2(acc[0], acc[1]);
        }
    }
}

// ---------------- launch -----------------------------------------------------
extern "C" void kernel_launch(void* const* d_in, const int* in_sizes, int n_in,
                              void* d_out, int out_size) {
    (void)n_in; (void)in_sizes; (void)out_size;
    const float* x      = (const float*)d_in[0];
    const int*   ei     = (const int*)d_in[1];
    const float* W1     = (const float*)d_in[2];
    const float* a_src1 = (const float*)d_in[3];
    const float* a_dst1 = (const float*)d_in[4];
    const float* b1     = (const float*)d_in[5];
    const float* W2     = (const float*)d_in[6];
    const float* a_src2 = (const float*)d_in[7];
    const float* a_dst2 = (const float*)d_in[8];
    const float* b2     = (const float*)d_in[9];
    float* dout = (float*)d_out;

    __half *h1, *out1, *h2;
    float *alsrc1, *aldst1, *alsrc2, *aldst2;
    cudaGetSymbolAddress((void**)&h1,     g_h1);
    cudaGetSymbolAddress((void**)&out1,   g_out1);
    cudaGetSymbolAddress((void**)&h2,     g_h2);
    cudaGetSymbolAddress((void**)&alsrc1, g_alsrc1);
    cudaGetSymbolAddress((void**)&aldst1, g_aldst1);
    cudaGetSymbolAddress((void**)&alsrc2, g_alsrc2);
    cudaGetSymbolAddress((void**)&aldst2, g_aldst2);

    const int T = 256;
    // 0) adjacency build (shared by both layers)
    init_kernel<<<(NN + T - 1) / T, T>>>();
    fill_adj<<<(ETOT + T - 1) / T, T>>>(ei);
    // 1) h1 = x @ W1 (+ als1/ald1 fused), h1 stored fp16
    {
        dim3 g(C1 / BN, (NN + BM - 1) / BM);
        gemm_mma_al<H1N, float><<<g, 256>>>(x, W1, h1, a_src1, a_dst1,
                                            alsrc1, aldst1, NN, 128, C1);
    }
    // 2) fused softmax + aggregate + bias + elu  (layer 1), out1 fp16
    csr_aggregate<H1N, C1, true, __half><<<(NN * 32 + T - 1) / T, T>>>(
        h1, alsrc1, aldst1, b1, out1);
    // 3) h2 = out1 @ W2 (+ als2/ald2 fused), fp16 A, h2 fp16
    {
        dim3 g(C2 / BN, (NN + BM - 1) / BM);
        gemm_mma_al<1, __half><<<g, 256>>>(out1, W2, h2, a_src2, a_dst2,
                                           alsrc2, aldst2, NN, C1, C2);
    }
    // 4) fused softmax + aggregate + bias  (layer 2, fp32 straight to d_out)
    csr_aggregate<1, C2, false, float><<<(NN * 32 + T - 1) / T, T>>>(
        h2, alsrc2, aldst2, b2, dout);
}

// round 7
// speedup vs baseline: 3.1828x; 1.1324x over previous
#include <cuda_runtime.h>
#include <cuda_fp16.h>
#include <math.h>

#define NN   50000
#define EE   800000
#define ETOT (EE + NN)
#define H1N  4
#define C1   256   // H1*64
#define C2   64
#define CAP  128   // per-destination adjacency capacity

#define BM 128
#define BN 64
#define BK 16

// ---------------- scratch (device globals; no allocations allowed) ----------
__device__ __half g_h1[(size_t)NN * C1];
__device__ __half g_out1[(size_t)NN * C1];
__device__ __half g_h2[(size_t)NN * C2];
__device__ float  g_alsrc1[NN * H1N], g_aldst1[NN * H1N];
__device__ float  g_alsrc2[NN],       g_aldst2[NN];
__device__ int    g_cursor[NN];
__device__ int    g_csr[(size_t)NN * CAP];

// ---------------- helpers ----------------------------------------------------
__device__ __forceinline__ float to_tf32(float x) {
    unsigned u;
    asm("cvt.rna.tf32.f32 %0, %1;" : "=r"(u) : "f"(x));
    return __uint_as_float(u);
}
__device__ __forceinline__ void mma_m16n8k8(float* c, const float* a, const float* b) {
    asm volatile("mma.sync.aligned.m16n8k8.row.col.f32.tf32.tf32.f32 "
        "{%0,%1,%2,%3}, {%4,%5,%6,%7}, {%8,%9}, {%0,%1,%2,%3};"
        : "+f"(c[0]), "+f"(c[1]), "+f"(c[2]), "+f"(c[3])
        : "r"(__float_as_uint(a[0])), "r"(__float_as_uint(a[1])),
          "r"(__float_as_uint(a[2])), "r"(__float_as_uint(a[3])),
          "r"(__float_as_uint(b[0])), "r"(__float_as_uint(b[1])));
}

// ---------------- adjacency build -------------------------------------------
__global__ void init_kernel() {
    int tid = blockIdx.x * blockDim.x + threadIdx.x;
    if (tid < NN) g_cursor[tid] = 0;
}
__global__ void fill_adj(const int* __restrict__ ei) {
    int e = blockIdx.x * blockDim.x + threadIdx.x;
    if (e >= ETOT) return;
    int s, d;
    if (e < EE) { s = ei[e]; d = ei[e + EE]; }
    else        { s = d = e - EE; }
    int pos = atomicAdd(&g_cursor[d], 1);
    if (pos < CAP) g_csr[(size_t)d * CAP + pos] = s;
}

// ---------------- tf32 mma GEMM + fused attention-coefficient epilogue ------
template <int H, typename AT>
__global__ __launch_bounds__(256, 2)
void gemm_mma_al(const AT* __restrict__ A, const float* __restrict__ B,
                 __half* __restrict__ C,
                 const float* __restrict__ asrc, const float* __restrict__ adst,
                 float* __restrict__ als, float* __restrict__ ald,
                 int M, int K, int N_) {
    __shared__ float As[BK][BM + 4];
    __shared__ float Bs[BK][BN + 4];
    __shared__ float red_s[2][BM], red_d[2][BM];

    const int t    = threadIdx.x;
    const int lane = t & 31, wid = t >> 5;
    const int wm = wid & 3, wn = wid >> 2;      // 4x2 warp grid
    const int grp = lane >> 2, tig = lane & 3;
    const int head = blockIdx.x;
    const int row0 = blockIdx.y * BM;
    const int col0 = head * BN;

    float acc[2][4][4] = {};

    for (int k0 = 0; k0 < K; k0 += BK) {
        if constexpr (sizeof(AT) == 4) {
            #pragma unroll
            for (int it = 0; it < 2; it++) {
                int idx = it * 256 + t;
                int rl = idx >> 2, c4 = (idx & 3) * 4;
                int gr = row0 + rl;
                float4 v = make_float4(0.f, 0.f, 0.f, 0.f);
                if (gr < M) v = *(const float4*)&A[(size_t)gr * K + k0 + c4];
                As[c4 + 0][rl] = to_tf32(v.x); As[c4 + 1][rl] = to_tf32(v.y);
                As[c4 + 2][rl] = to_tf32(v.z); As[c4 + 3][rl] = to_tf32(v.w);
            }
        } else {
            int rl = t >> 1, c8 = (t & 1) * 8;
            int gr = row0 + rl;
            uint4 u = make_uint4(0u, 0u, 0u, 0u);
            if (gr < M) u = *(const uint4*)&A[(size_t)gr * K + k0 + c8];
            const __half2* hp = (const __half2*)&u;
            #pragma unroll
            for (int j = 0; j < 4; j++) {
                float2 f = __half22float2(hp[j]);
                As[c8 + j * 2 + 0][rl] = f.x;
                As[c8 + j * 2 + 1][rl] = f.y;
            }
        }
        {
            int rl = t >> 4, c4 = (t & 15) * 4;
            float4 v = *(const float4*)&B[(size_t)(k0 + rl) * N_ + col0 + c4];
            *(float4*)&Bs[rl][c4] = make_float4(to_tf32(v.x), to_tf32(v.y),
                                                to_tf32(v.z), to_tf32(v.w));
        }
        __syncthreads();

        #pragma unroll
        for (int kk = 0; kk < BK; kk += 8) {
            float a[2][4], b[4][2];
            #pragma unroll
            for (int mt = 0; mt < 2; mt++) {
                int m0 = wm * 32 + mt * 16;
                a[mt][0] = As[kk + tig][m0 + grp];
                a[mt][1] = As[kk + tig][m0 + grp + 8];
                a[mt][2] = As[kk + tig + 4][m0 + grp];
                a[mt][3] = As[kk + tig + 4][m0 + grp + 8];
            }
            #pragma unroll
            for (int nt = 0; nt < 4; nt++) {
                int n0 = wn * 32 + nt * 8;
                b[nt][0] = Bs[kk + tig][n0 + grp];
                b[nt][1] = Bs[kk + tig + 4][n0 + grp];
            }
            #pragma unroll
            for (int mt = 0; mt < 2; mt++)
                #pragma unroll
                for (int nt = 0; nt < 4; nt++)
                    mma_m16n8k8(acc[mt][nt], a[mt], b[nt]);
        }
        __syncthreads();
    }

    float ps[2][2] = {}, pd[2][2] = {};
    #pragma unroll
    for (int mt = 0; mt < 2; mt++) {
        int r0 = row0 + wm * 32 + mt * 16 + grp;
        #pragma unroll
        for (int nt = 0; nt < 4; nt++) {
            int cih = wn * 32 + nt * 8 + tig * 2;
            float c0 = acc[mt][nt][0], c1 = acc[mt][nt][1];
            float c2 = acc[mt][nt][2], c3 = acc[mt][nt][3];
            if (r0 < M)
                *(__half2*)&C[(size_t)r0 * N_ + col0 + cih] = __floats2half2_rn(c0, c1);
            if (r0 + 8 < M)
                *(__half2*)&C[(size_t)(r0 + 8) * N_ + col0 + cih] = __floats2half2_rn(c2, c3);
            float as0 = asrc[head * 64 + cih], as1 = asrc[head * 64 + cih + 1];
            float ad0 = adst[head * 64 + cih], ad1 = adst[head * 64 + cih + 1];
            ps[mt][0] += c0 * as0 + c1 * as1;  ps[mt][1] += c2 * as0 + c3 * as1;
            pd[mt][0] += c0 * ad0 + c1 * ad1;  pd[mt][1] += c2 * ad0 + c3 * ad1;
        }
    }
    #pragma unroll
    for (int mt = 0; mt < 2; mt++)
        #pragma unroll
        for (int rh = 0; rh < 2; rh++) {
            float s = ps[mt][rh], d = pd[mt][rh];
            s += __shfl_xor_sync(0xffffffffu, s, 1);
            s += __shfl_xor_sync(0xffffffffu, s, 2);
            d += __shfl_xor_sync(0xffffffffu, d, 1);
            d += __shfl_xor_sync(0xffffffffu, d, 2);
            if (tig == 0) {
                int rloc = wm * 32 + mt * 16 + rh * 8 + grp;
                red_s[wn][rloc] = s;
                red_d[wn][rloc] = d;
            }
        }
    __syncthreads();
    if (t < BM) {
        int row = row0 + t;
        if (row < M) {
            als[(size_t)row * H + head] = red_s[0][t] + red_s[1][t];
            ald[(size_t)row * H + head] = red_d[0][t] + red_d[1][t];
        }
    }
}

// ---------------- single-pass softmax aggregation ----------------------------
// Key identity: softmax-weighted sum = (Σ e_i·v_i) / (Σ e_i); no per-edge
// alpha, no separate denominator pass. One edge loop: e = exp(leaky(logit)),
// den += e, acc += e·feat. Normalize + bias + elu in the epilogue.
// Edge list read as int4 (1 broadcast LDG / 4 edges, 4 feature loads in flight).
template <int H, int TC, bool DO_ELU, typename OutT>
__global__ __launch_bounds__(256)
void csr_aggregate(const __half* __restrict__ feat,
                   const float* __restrict__ als,
                   const float* __restrict__ ald,
                   const float* __restrict__ bias,
                   OutT* __restrict__ out) {
    int gw = (blockIdx.x * blockDim.x + threadIdx.x) >> 5;   // destination node
    if (gw >= NN) return;
    const int lane = threadIdx.x & 31;
    constexpr int FPL = TC / 32;                              // 8 / 2 halves per lane
    const int col = lane * FPL;
    const int myh = (H == 1) ? 0 : (col >> 6);

    const float aldh = ald[gw * H + myh];
    const int dg = min(g_cursor[gw], CAP);
    const int* lst = &g_csr[(size_t)gw * CAP];
    const int4* lst4 = (const int4*)lst;      // 512B-aligned (CAP ints)

    float den = 0.f;
    float acc[FPL] = {};

    auto edge = [&](int s) {
        float l = als[s * H + myh] + aldh;
        l = fmaxf(l, 0.f) + 0.2f * fminf(l, 0.f);
        float e = __expf(l);
        den += e;
        const __half* row = &feat[(size_t)s * TC + col];
        if constexpr (FPL == 8) {
            uint4 u = *(const uint4*)row;
            const __half2* hp = (const __half2*)&u;
            #pragma unroll
            for (int j = 0; j < 4; j++) {
                float2 f = __half22float2(hp[j]);
                acc[j * 2 + 0] += e * f.x;
                acc[j * 2 + 1] += e * f.y;
            }
        } else {
            float2 f = __half22float2(*(const __half2*)row);
            acc[0] += e * f.x;
            acc[1] += e * f.y;
        }
    };

    const int nv = dg >> 2;
    for (int iv = 0; iv < nv; iv++) {
        int4 q = lst4[iv];
        edge(q.x); edge(q.y); edge(q.z); edge(q.w);
    }
    for (int i = nv * 4; i < dg; i++) edge(lst[i]);

    // epilogue: normalize, bias (+ elu), store
    const float rden = 1.f / fmaxf(den, 1e-16f);
    #pragma unroll
    for (int j = 0; j < FPL; j++) {
        float v = acc[j] * rden + bias[col + j];
        if constexpr (DO_ELU) v = v > 0.f ? v : expm1f(v);
        acc[j] = v;
    }
    if constexpr (sizeof(OutT) == 2) {
        __half2 hv[FPL / 2];
        #pragma unroll
        for (int j = 0; j < FPL / 2; j++)
            hv[j] = __floats2half2_rn(acc[j * 2], acc[j * 2 + 1]);
        if constexpr (FPL == 8)
            *(uint4*)&out[(size_t)gw * TC + col] = *(uint4*)hv;
        else
            *(__half2*)&out[(size_t)gw * TC + col] = hv[0];
    } else {
        if constexpr (FPL == 8) {
            *(float4*)&out[(size_t)gw * TC + col]     = make_float4(acc[0], acc[1], acc[2], acc[3]);
            *(float4*)&out[(size_t)gw * TC + col + 4] = make_float4(acc[4], acc[5], acc[6], acc[7]);
        } else {
            *(float2*)&out[(size_t)gw * TC + col] = make_float2(acc[0], acc[1]);
        }
    }
}

// ---------------- launch -----------------------------------------------------
extern "C" void kernel_launch(void* const* d_in, const int* in_sizes, int n_in,
                              void* d_out, int out_size) {
    (void)n_in; (void)in_sizes; (void)out_size;
    const float* x      = (const float*)d_in[0];
    const int*   ei     = (const int*)d_in[1];
    const float* W1     = (const float*)d_in[2];
    const float* a_src1 = (const float*)d_in[3];
    const float* a_dst1 = (const float*)d_in[4];
    const float* b1     = (const float*)d_in[5];
    const float* W2     = (const float*)d_in[6];
    const float* a_src2 = (const float*)d_in[7];
    const float* a_dst2 = (const float*)d_in[8];
    const float* b2     = (const float*)d_in[9];
    float* dout = (float*)d_out;

    __half *h1, *out1, *h2;
    float *alsrc1, *aldst1, *alsrc2, *aldst2;
    cudaGetSymbolAddress((void**)&h1,     g_h1);
    cudaGetSymbolAddress((void**)&out1,   g_out1);
    cudaGetSymbolAddress((void**)&h2,     g_h2);
    cudaGetSymbolAddress((void**)&alsrc1, g_alsrc1);
    cudaGetSymbolAddress((void**)&aldst1, g_aldst1);
    cudaGetSymbolAddress((void**)&alsrc2, g_alsrc2);
    cudaGetSymbolAddress((void**)&aldst2, g_aldst2);

    const int T = 256;
    // 0) adjacency build (shared by both layers)
    init_kernel<<<(NN + T - 1) / T, T>>>();
    fill_adj<<<(ETOT + T - 1) / T, T>>>(ei);
    // 1) h1 = x @ W1 (+ als1/ald1 fused), h1 stored fp16
    {
        dim3 g(C1 / BN, (NN + BM - 1) / BM);
        gemm_mma_al<H1N, float><<<g, 256>>>(x, W1, h1, a_src1, a_dst1,
                                            alsrc1, aldst1, NN, 128, C1);
    }
    // 2) single-pass softmax + aggregate + bias + elu  (layer 1), out1 fp16
    csr_aggregate<H1N, C1, true, __half><<<(NN * 32 + T - 1) / T, T>>>(
        h1, alsrc1, aldst1, b1, out1);
    // 3) h2 = out1 @ W2 (+ als2/ald2 fused), fp16 A, h2 fp16
    {
        dim3 g(C2 / BN, (NN + BM - 1) / BM);
        gemm_mma_al<1, __half><<<g, 256>>>(out1, W2, h2, a_src2, a_dst2,
                                           alsrc2, aldst2, NN, C1, C2);
    }
    // 4) single-pass softmax + aggregate + bias  (layer 2, fp32 to d_out)
    csr_aggregate<1, C2, false, float><<<(NN * 32 + T - 1) / T, T>>>(
        h2, alsrc2, aldst2, b2, dout);
}

// round 8
// speedup vs baseline: 3.7146x; 1.1671x over previous
#include <cuda_runtime.h>
#include <cuda_fp16.h>
#include <math.h>

#define NN   50000
#define EE   800000
#define ETOT (EE + NN)
#define H1N  4
#define C1   256   // H1*64
#define C2   64
#define CAP  128   // per-destination adjacency capacity

#define BM 128
#define BN 64
#define BK 16
#define APAD 24    // As row stride in halves (48B: 16B-aligned, spread banks)
#define BPAD 26    // Bs row stride in halves (52B: spread banks)

// ---------------- scratch (device globals; no allocations allowed) ----------
__device__ __half g_h1[(size_t)NN * C1];
__device__ __half g_out1[(size_t)NN * C1];
__device__ __half g_h2[(size_t)NN * C2];
__device__ float  g_alsrc1[NN * H1N], g_aldst1[NN * H1N];
__device__ float  g_alsrc2[NN],       g_aldst2[NN];
__device__ int    g_cursor[NN];
__device__ int    g_csr[(size_t)NN * CAP];

// ---------------- helpers ----------------------------------------------------
__device__ __forceinline__ void mma_f16(float* c, const unsigned* a, const unsigned* b) {
    asm volatile("mma.sync.aligned.m16n8k16.row.col.f32.f16.f16.f32 "
        "{%0,%1,%2,%3}, {%4,%5,%6,%7}, {%8,%9}, {%0,%1,%2,%3};"
        : "+f"(c[0]), "+f"(c[1]), "+f"(c[2]), "+f"(c[3])
        : "r"(a[0]), "r"(a[1]), "r"(a[2]), "r"(a[3]), "r"(b[0]), "r"(b[1]));
}
// packed f32x2 FMA: acc += float2(h2) * e2   (FFMA2 path, sm_100+)
__device__ __forceinline__ void ffma2_h2(unsigned long long& acc, unsigned h2,
                                         unsigned long long e2) {
    asm("{\n\t"
        ".reg .b16 h0, h1;\n\t"
        ".reg .f32 lo, hi;\n\t"
        ".reg .b64 v;\n\t"
        "mov.b32 {h0, h1}, %1;\n\t"
        "cvt.f32.f16 lo, h0;\n\t"
        "cvt.f32.f16 hi, h1;\n\t"
        "mov.b64 v, {lo, hi};\n\t"
        "fma.rn.f32x2 %0, v, %2, %0;\n\t"
        "}" : "+l"(acc) : "r"(h2), "l"(e2));
}
__device__ __forceinline__ unsigned long long pack2(float e) {
    unsigned long long r;
    asm("mov.b64 %0, {%1, %1};" : "=l"(r) : "f"(e));
    return r;
}
__device__ __forceinline__ float2 unpack2(unsigned long long v) {
    float2 f;
    asm("mov.b64 {%0, %1}, %2;" : "=f"(f.x), "=f"(f.y) : "l"(v));
    return f;
}

// ---------------- adjacency build -------------------------------------------
__global__ void init_kernel() {
    int tid = blockIdx.x * blockDim.x + threadIdx.x;
    if (tid < NN) g_cursor[tid] = 0;
}
__global__ void fill_adj(const int* __restrict__ ei) {
    int e = blockIdx.x * blockDim.x + threadIdx.x;
    if (e >= ETOT) return;
    int s, d;
    if (e < EE) { s = ei[e]; d = ei[e + EE]; }
    else        { s = d = e - EE; }
    int pos = atomicAdd(&g_cursor[d], 1);
    if (pos < CAP) g_csr[(size_t)d * CAP + pos] = s;
}

// ---------------- fp16 HMMA GEMM + fused attention-coefficient epilogue ------
// A fp32 or fp16 (templated, converted to fp16 in staging — fp16 mantissa ==
// tf32 mantissa, so no precision loss vs the tf32 path); B fp32 -> fp16.
// C stored fp16; al_src/al_dst dots fused in the fp32-accumulator epilogue.
template <int H, typename AT>
__global__ __launch_bounds__(256, 2)
void gemm_mma_al(const AT* __restrict__ A, const float* __restrict__ B,
                 __half* __restrict__ C,
                 const float* __restrict__ asrc, const float* __restrict__ adst,
                 float* __restrict__ als, float* __restrict__ ald,
                 int M, int K, int N_) {
    __shared__ alignas(16) __half As[BM][APAD];   // [m][k], k contiguous
    __shared__ alignas(16) __half Bs[BN][BPAD];   // [n][k], k contiguous
    __shared__ float red_s[2][BM], red_d[2][BM];

    const int t    = threadIdx.x;
    const int lane = t & 31, wid = t >> 5;
    const int wm = wid & 3, wn = wid >> 2;      // 4x2 warp grid (32x32 warp tile)
    const int grp = lane >> 2, tig = lane & 3;
    const int head = blockIdx.x;
    const int row0 = blockIdx.y * BM;
    const int col0 = head * BN;

    float acc[2][4][4] = {};

    for (int k0 = 0; k0 < K; k0 += BK) {
        // ---- stage A: [BM][BK] fp16, thread owns 8 k-contiguous halves ----
        {
            int rl = t >> 1, c8 = (t & 1) * 8;
            int gr = row0 + rl;
            __half2 hv[4];
            if constexpr (sizeof(AT) == 4) {
                float4 v1 = make_float4(0.f, 0.f, 0.f, 0.f);
                float4 v2 = make_float4(0.f, 0.f, 0.f, 0.f);
                if (gr < M) {
                    v1 = *(const float4*)&A[(size_t)gr * K + k0 + c8];
                    v2 = *(const float4*)&A[(size_t)gr * K + k0 + c8 + 4];
                }
                hv[0] = __floats2half2_rn(v1.x, v1.y);
                hv[1] = __floats2half2_rn(v1.z, v1.w);
                hv[2] = __floats2half2_rn(v2.x, v2.y);
                hv[3] = __floats2half2_rn(v2.z, v2.w);
            } else {
                uint4 u = make_uint4(0u, 0u, 0u, 0u);
                if (gr < M) u = *(const uint4*)&A[(size_t)gr * K + k0 + c8];
                *(uint4*)hv = u;
            }
            *(uint4*)&As[rl][c8] = *(uint4*)hv;
        }
        // ---- stage B: [BN][BK] fp16 (transpose of gmem [K][N_]) ----
        {
            int kk = t >> 4, n4 = (t & 15) * 4;
            float4 v = *(const float4*)&B[(size_t)(k0 + kk) * N_ + col0 + n4];
            Bs[n4 + 0][kk] = __float2half_rn(v.x);
            Bs[n4 + 1][kk] = __float2half_rn(v.y);
            Bs[n4 + 2][kk] = __float2half_rn(v.z);
            Bs[n4 + 3][kk] = __float2half_rn(v.w);
        }
        __syncthreads();

        // ---- fragments + 8 HMMA per chunk ----
        unsigned a[2][4], b[4][2];
        #pragma unroll
        for (int mt = 0; mt < 2; mt++) {
            int m0 = wm * 32 + mt * 16;
            a[mt][0] = *(const unsigned*)&As[m0 + grp][tig * 2];
            a[mt][1] = *(const unsigned*)&As[m0 + grp + 8][tig * 2];
            a[mt][2] = *(const unsigned*)&As[m0 + grp][tig * 2 + 8];
            a[mt][3] = *(const unsigned*)&As[m0 + grp + 8][tig * 2 + 8];
        }
        #pragma unroll
        for (int nt = 0; nt < 4; nt++) {
            int n0 = wn * 32 + nt * 8;
            b[nt][0] = *(const unsigned*)&Bs[n0 + grp][tig * 2];
            b[nt][1] = *(const unsigned*)&Bs[n0 + grp][tig * 2 + 8];
        }
        #pragma unroll
        for (int mt = 0; mt < 2; mt++)
            #pragma unroll
            for (int nt = 0; nt < 4; nt++)
                mma_f16(acc[mt][nt], a[mt], b[nt]);
        __syncthreads();
    }

    // ---- epilogue: fp16 store + fused al_src/al_dst dots (fp32) ----
    float ps[2][2] = {}, pd[2][2] = {};
    #pragma unroll
    for (int mt = 0; mt < 2; mt++) {
        int r0 = row0 + wm * 32 + mt * 16 + grp;
        #pragma unroll
        for (int nt = 0; nt < 4; nt++) {
            int cih = wn * 32 + nt * 8 + tig * 2;
            float c0 = acc[mt][nt][0], c1 = acc[mt][nt][1];
            float c2 = acc[mt][nt][2], c3 = acc[mt][nt][3];
            if (r0 < M)
                *(__half2*)&C[(size_t)r0 * N_ + col0 + cih] = __floats2half2_rn(c0, c1);
            if (r0 + 8 < M)
                *(__half2*)&C[(size_t)(r0 + 8) * N_ + col0 + cih] = __floats2half2_rn(c2, c3);
            float as0 = asrc[head * 64 + cih], as1 = asrc[head * 64 + cih + 1];
            float ad0 = adst[head * 64 + cih], ad1 = adst[head * 64 + cih + 1];
            ps[mt][0] += c0 * as0 + c1 * as1;  ps[mt][1] += c2 * as0 + c3 * as1;
            pd[mt][0] += c0 * ad0 + c1 * ad1;  pd[mt][1] += c2 * ad0 + c3 * ad1;
        }
    }
    #pragma unroll
    for (int mt = 0; mt < 2; mt++)
        #pragma unroll
        for (int rh = 0; rh < 2; rh++) {
            float s = ps[mt][rh], d = pd[mt][rh];
            s += __shfl_xor_sync(0xffffffffu, s, 1);
            s += __shfl_xor_sync(0xffffffffu, s, 2);
            d += __shfl_xor_sync(0xffffffffu, d, 1);
            d += __shfl_xor_sync(0xffffffffu, d, 2);
            if (tig == 0) {
                int rloc = wm * 32 + mt * 16 + rh * 8 + grp;
                red_s[wn][rloc] = s;
                red_d[wn][rloc] = d;
            }
        }
    __syncthreads();
    if (t < BM) {
        int row = row0 + t;
        if (row < M) {
            als[(size_t)row * H + head] = red_s[0][t] + red_s[1][t];
            ald[(size_t)row * H + head] = red_d[0][t] + red_d[1][t];
        }
    }
}

// ---------------- single-pass softmax aggregation ----------------------------
// softmax-weighted sum = (Σ e_i·v_i) / (Σ e_i). One edge loop; accumulation
// via packed fma.rn.f32x2 (FFMA2) on fp32 pairs.
template <int H, int TC, bool DO_ELU, typename OutT>
__global__ __launch_bounds__(256)
void csr_aggregate(const __half* __restrict__ feat,
                   const float* __restrict__ als,
                   const float* __restrict__ ald,
                   const float* __restrict__ bias,
                   OutT* __restrict__ out) {
    int gw = (blockIdx.x * blockDim.x + threadIdx.x) >> 5;   // destination node
    if (gw >= NN) return;
    const int lane = threadIdx.x & 31;
    constexpr int FPL = TC / 32;                              // 8 / 2 halves per lane
    constexpr int NP  = FPL / 2;                              // packed f32x2 accumulators
    const int col = lane * FPL;
    const int myh = (H == 1) ? 0 : (col >> 6);

    const float aldh = ald[gw * H + myh];
    const int dg = min(g_cursor[gw], CAP);
    const int* lst = &g_csr[(size_t)gw * CAP];
    const int4* lst4 = (const int4*)lst;      // 512B-aligned (CAP ints)

    float den = 0.f;
    unsigned long long acc[NP] = {};

    auto edge = [&](int s) {
        float l = als[s * H + myh] + aldh;
        l = fmaxf(l, 0.f) + 0.2f * fminf(l, 0.f);
        float e = __expf(l);
        den += e;
        unsigned long long e2 = pack2(e);
        const __half* row = &feat[(size_t)s * TC + col];
        if constexpr (FPL == 8) {
            uint4 u = *(const uint4*)row;
            ffma2_h2(acc[0], u.x, e2);
            ffma2_h2(acc[1], u.y, e2);
            ffma2_h2(acc[2], u.z, e2);
            ffma2_h2(acc[3], u.w, e2);
        } else {
            unsigned u = *(const unsigned*)row;
            ffma2_h2(acc[0], u, e2);
        }
    };

    const int nv = dg >> 2;
    for (int iv = 0; iv < nv; iv++) {
        int4 q = lst4[iv];
        edge(q.x); edge(q.y); edge(q.z); edge(q.w);
    }
    for (int i = nv * 4; i < dg; i++) edge(lst[i]);

    // epilogue: normalize, bias (+ elu), store
    const float rden = 1.f / fmaxf(den, 1e-16f);
    float res[FPL];
    #pragma unroll
    for (int p = 0; p < NP; p++) {
        float2 f = unpack2(acc[p]);
        res[p * 2 + 0] = f.x; res[p * 2 + 1] = f.y;
    }
    #pragma unroll
    for (int j = 0; j < FPL; j++) {
        float v = res[j] * rden + bias[col + j];
        if constexpr (DO_ELU) v = v > 0.f ? v : expm1f(v);
        res[j] = v;
    }
    if constexpr (sizeof(OutT) == 2) {
        __half2 hv[NP];
        #pragma unroll
        for (int j = 0; j < NP; j++)
            hv[j] = __floats2half2_rn(res[j * 2], res[j * 2 + 1]);
        if constexpr (FPL == 8)
            *(uint4*)&out[(size_t)gw * TC + col] = *(uint4*)hv;
        else
            *(__half2*)&out[(size_t)gw * TC + col] = hv[0];
    } else {
        if constexpr (FPL == 8) {
            *(float4*)&out[(size_t)gw * TC + col]     = make_float4(res[0], res[1], res[2], res[3]);
            *(float4*)&out[(size_t)gw * TC + col + 4] = make_float4(res[4], res[5], res[6], res[7]);
        } else {
            *(float2*)&out[(size_t)gw * TC + col] = make_float2(res[0], res[1]);
        }
    }
}

// ---------------- launch -----------------------------------------------------
extern "C" void kernel_launch(void* const* d_in, const int* in_sizes, int n_in,
                              void* d_out, int out_size) {
    (void)n_in; (void)in_sizes; (void)out_size;
    const float* x      = (const float*)d_in[0];
    const int*   ei     = (const int*)d_in[1];
    const float* W1     = (const float*)d_in[2];
    const float* a_src1 = (const float*)d_in[3];
    const float* a_dst1 = (const float*)d_in[4];
    const float* b1     = (const float*)d_in[5];
    const float* W2     = (const float*)d_in[6];
    const float* a_src2 = (const float*)d_in[7];
    const float* a_dst2 = (const float*)d_in[8];
    const float* b2     = (const float*)d_in[9];
    float* dout = (float*)d_out;

    __half *h1, *out1, *h2;
    float *alsrc1, *aldst1, *alsrc2, *aldst2;
    cudaGetSymbolAddress((void**)&h1,     g_h1);
    cudaGetSymbolAddress((void**)&out1,   g_out1);
    cudaGetSymbolAddress((void**)&h2,     g_h2);
    cudaGetSymbolAddress((void**)&alsrc1, g_alsrc1);
    cudaGetSymbolAddress((void**)&aldst1, g_aldst1);
    cudaGetSymbolAddress((void**)&alsrc2, g_alsrc2);
    cudaGetSymbolAddress((void**)&aldst2, g_aldst2);

    const int T = 256;
    // 0) adjacency build (shared by both layers)
    init_kernel<<<(NN + T - 1) / T, T>>>();
    fill_adj<<<(ETOT + T - 1) / T, T>>>(ei);
    // 1) h1 = x @ W1 (+ als1/ald1 fused), fp16 HMMA, h1 stored fp16
    {
        dim3 g(C1 / BN, (NN + BM - 1) / BM);
        gemm_mma_al<H1N, float><<<g, 256>>>(x, W1, h1, a_src1, a_dst1,
                                            alsrc1, aldst1, NN, 128, C1);
    }
    // 2) single-pass softmax + aggregate + bias + elu  (layer 1), out1 fp16
    csr_aggregate<H1N, C1, true, __half><<<(NN * 32 + T - 1) / T, T>>>(
        h1, alsrc1, aldst1, b1, out1);
    // 3) h2 = out1 @ W2 (+ als2/ald2 fused), fp16 A direct, fp16 HMMA
    {
        dim3 g(C2 / BN, (NN + BM - 1) / BM);
        gemm_mma_al<1, __half><<<g, 256>>>(out1, W2, h2, a_src2, a_dst2,
                                           alsrc2, aldst2, NN, C1, C2);
    }
    // 4) single-pass softmax + aggregate + bias  (layer 2, fp32 to d_out)
    csr_aggregate<1, C2, false, float><<<(NN * 32 + T - 1) / T, T>>>(
        h2, alsrc2, aldst2, b2, dout);
}